// round 6
// baseline (speedup 1.0000x reference)
#include <cuda_runtime.h>
#include <cuda_fp16.h>
#include <mma.h>
#include <math.h>

using namespace nvcuda;

#define DIM 256
#define H1D 128
#define H2D 64
#define TILE_ROWS 128
#define THREADS 256

// smem layout (bytes):
//  sW1h : half [256][136]              -> 69632
//  sW2h : half [128][72]               -> 18432
//  region C (union):
//     sXh  : half  [128][264] = 67584
//     sH1f : float [128][132] = 67584
//     sH2f : float [128][68]  = 34816
//  sH1h : half [128][136]              -> 34816
//  sb   : float[257] (b1[128],b2[64],W3[64],b3) -> pad 1040
#define OFF_W1 0
#define OFF_W2 69632
#define OFF_C  (69632 + 18432)
#define OFF_H1H (OFF_C + 67584)
#define OFF_B   (OFF_H1H + 34816)
#define SMEM_BYTES (OFF_B + 1040)

// scratch (device globals; no allocation allowed)
__device__ float g_logits[620000];
__device__ float g_m[4096];
__device__ float g_s[4096];

__global__ void __launch_bounds__(THREADS)
mlp_logits_kernel(const float* __restrict__ X,
                  const float* __restrict__ W1, const float* __restrict__ b1,
                  const float* __restrict__ W2, const float* __restrict__ b2,
                  const float* __restrict__ W3, const float* __restrict__ b3,
                  float* __restrict__ logits, int nrows)
{
    extern __shared__ char smem[];
    half*  sW1h = (half*)(smem + OFF_W1);
    half*  sW2h = (half*)(smem + OFF_W2);
    half*  sXh  = (half*)(smem + OFF_C);
    float* sH1f = (float*)(smem + OFF_C);
    float* sH2f = (float*)(smem + OFF_C);
    half*  sH1h = (half*)(smem + OFF_H1H);
    float* sb   = (float*)(smem + OFF_B);

    const int tid = threadIdx.x;
    const int w   = tid >> 5;
    const int rowBase = blockIdx.x * TILE_ROWS;

    // load weights (fp32 -> fp16) and biases into smem
    for (int i = tid; i < 256 * 128; i += THREADS)
        sW1h[(i >> 7) * 136 + (i & 127)] = __float2half(W1[i]);
    for (int i = tid; i < 128 * 64; i += THREADS)
        sW2h[(i >> 6) * 72 + (i & 63)] = __float2half(W2[i]);
    if (tid < 128) sb[tid] = b1[tid];
    if (tid < 64) {
        sb[128 + tid] = b2[tid];
        sb[192 + tid] = W3[tid];
    }
    if (tid == 0) sb[256] = b3[0];

    // load X tile (fp32 -> fp16), zero-pad tail rows
    for (int i = tid; i < TILE_ROWS * DIM; i += THREADS) {
        int r = i >> 8, c = i & 255;
        int gr = rowBase + r;
        float v = (gr < nrows) ? X[(size_t)gr * DIM + c] : 0.0f;
        sXh[r * 264 + c] = __float2half(v);
    }
    __syncthreads();

    // ---- GEMM1: H1[128x128] = X[128x256] @ W1[256x128] ----
    {
        wmma::fragment<wmma::accumulator, 16, 16, 16, float> acc[8];
#pragma unroll
        for (int n = 0; n < 8; n++) wmma::fill_fragment(acc[n], 0.0f);
#pragma unroll
        for (int kt = 0; kt < 16; kt++) {
            wmma::fragment<wmma::matrix_a, 16, 16, 16, half, wmma::row_major> a;
            wmma::load_matrix_sync(a, sXh + (w * 16) * 264 + kt * 16, 264);
#pragma unroll
            for (int n = 0; n < 8; n++) {
                wmma::fragment<wmma::matrix_b, 16, 16, 16, half, wmma::row_major> b;
                wmma::load_matrix_sync(b, sW1h + (kt * 16) * 136 + n * 16, 136);
                wmma::mma_sync(acc[n], a, b, acc[n]);
            }
        }
        __syncthreads();  // all warps done reading sXh before overwriting region C
#pragma unroll
        for (int n = 0; n < 8; n++)
            wmma::store_matrix_sync(sH1f + (w * 16) * 132 + n * 16, acc[n], 132,
                                    wmma::mem_row_major);
    }
    __syncthreads();

    // bias + relu + convert to fp16
    for (int i = tid; i < 128 * 128; i += THREADS) {
        int r = i >> 7, c = i & 127;
        float v = sH1f[r * 132 + c] + sb[c];
        sH1h[r * 136 + c] = __float2half(fmaxf(v, 0.0f));
    }
    __syncthreads();

    // ---- GEMM2: H2[128x64] = H1[128x128] @ W2[128x64] ----
    {
        wmma::fragment<wmma::accumulator, 16, 16, 16, float> acc2[4];
#pragma unroll
        for (int n = 0; n < 4; n++) wmma::fill_fragment(acc2[n], 0.0f);
#pragma unroll
        for (int kt = 0; kt < 8; kt++) {
            wmma::fragment<wmma::matrix_a, 16, 16, 16, half, wmma::row_major> a;
            wmma::load_matrix_sync(a, sH1h + (w * 16) * 136 + kt * 16, 136);
#pragma unroll
            for (int n = 0; n < 4; n++) {
                wmma::fragment<wmma::matrix_b, 16, 16, 16, half, wmma::row_major> b;
                wmma::load_matrix_sync(b, sW2h + (kt * 16) * 72 + n * 16, 72);
                wmma::mma_sync(acc2[n], a, b, acc2[n]);
            }
        }
        // region C currently holds stale H1f (fully consumed); safe to store
#pragma unroll
        for (int n = 0; n < 4; n++)
            wmma::store_matrix_sync(sH2f + (w * 16) * 68 + n * 16, acc2[n], 68,
                                    wmma::mem_row_major);
    }
    __syncthreads();

    // ---- layer 3: logit = b3 + sum_c relu(H2 + b2) * W3 ----
    if (tid < 128) {
        int r = tid;
        float acc = sb[256];
#pragma unroll
        for (int c = 0; c < 64; c++) {
            float v = fmaxf(sH2f[r * 68 + c] + sb[128 + c], 0.0f);
            acc = fmaf(v, sb[192 + c], acc);
        }
        int gr = rowBase + r;
        if (gr < nrows) logits[gr] = acc;
    }
}

__device__ __forceinline__ void seg_bounds(const int* __restrict__ index, int n,
                                           int g, int* sse)
{
    if (threadIdx.x < 2) {
        int target = g + (int)threadIdx.x;
        int lo = 0, hi = n;
        while (lo < hi) {
            int mid = (lo + hi) >> 1;
            if (index[mid] < target) lo = mid + 1; else hi = mid;
        }
        sse[threadIdx.x] = lo;
    }
}

__global__ void __launch_bounds__(256)
seg_stats_kernel(const float* __restrict__ logits, const int* __restrict__ index,
                 int n, float* __restrict__ m_out, float* __restrict__ s_out)
{
    __shared__ int sse[2];
    __shared__ float red[8];
    int g = blockIdx.x;
    seg_bounds(index, n, g, sse);
    __syncthreads();
    int start = sse[0], end = sse[1];
    int tid = threadIdx.x, lane = tid & 31, warp = tid >> 5;

    // max reduce
    float m = -INFINITY;
    for (int i = start + tid; i < end; i += 256) m = fmaxf(m, logits[i]);
#pragma unroll
    for (int off = 16; off; off >>= 1) m = fmaxf(m, __shfl_xor_sync(0xffffffffu, m, off));
    if (lane == 0) red[warp] = m;
    __syncthreads();
    if (tid == 0) {
        float mm = red[0];
#pragma unroll
        for (int i = 1; i < 8; i++) mm = fmaxf(mm, red[i]);
        red[0] = mm;
    }
    __syncthreads();
    m = red[0];
    __syncthreads();

    // sum exp reduce
    float s = 0.0f;
    for (int i = start + tid; i < end; i += 256) s += __expf(logits[i] - m);
#pragma unroll
    for (int off = 16; off; off >>= 1) s += __shfl_xor_sync(0xffffffffu, s, off);
    if (lane == 0) red[warp] = s;
    __syncthreads();
    if (tid == 0) {
        float ss = 0.0f;
#pragma unroll
        for (int i = 0; i < 8; i++) ss += red[i];
        m_out[g] = (end > start) ? m : 0.0f;
        s_out[g] = (end > start) ? ss : 0.0f;
    }
}

__global__ void __launch_bounds__(256)
pool_kernel(const float* __restrict__ X, const float* __restrict__ logits,
            const int* __restrict__ index, const float* __restrict__ m_arr,
            const float* __restrict__ s_arr, float* __restrict__ out, int n)
{
    __shared__ int sse[2];
    int g = blockIdx.x;
    seg_bounds(index, n, g, sse);
    __syncthreads();
    int start = sse[0], end = sse[1];
    int d = threadIdx.x;

    float m = m_arr[g];
    float sinv = (end > start) ? 1.0f / s_arr[g] : 0.0f;

    float a0 = 0.f, a1 = 0.f, a2 = 0.f, a3 = 0.f;
    int i = start;
    for (; i + 3 < end; i += 4) {
        float w0 = __expf(logits[i + 0] - m);
        float w1 = __expf(logits[i + 1] - m);
        float w2 = __expf(logits[i + 2] - m);
        float w3 = __expf(logits[i + 3] - m);
        a0 = fmaf(w0, X[(size_t)(i + 0) * DIM + d], a0);
        a1 = fmaf(w1, X[(size_t)(i + 1) * DIM + d], a1);
        a2 = fmaf(w2, X[(size_t)(i + 2) * DIM + d], a2);
        a3 = fmaf(w3, X[(size_t)(i + 3) * DIM + d], a3);
    }
    for (; i < end; i++) {
        float w0 = __expf(logits[i] - m);
        a0 = fmaf(w0, X[(size_t)i * DIM + d], a0);
    }
    float acc = (a0 + a1) + (a2 + a3);
    out[(size_t)g * DIM + d] = acc * sinv;
}

extern "C" void kernel_launch(void* const* d_in, const int* in_sizes, int n_in,
                              void* d_out, int out_size)
{
    const float* emb_nodes  = (const float*)d_in[0];
    const float* emb_edges  = (const float*)d_in[1];
    const int*   node_index = (const int*)d_in[2];
    const int*   edge_index = (const int*)d_in[3];
    const float* Wn1 = (const float*)d_in[4];
    const float* bn1 = (const float*)d_in[5];
    const float* Wn2 = (const float*)d_in[6];
    const float* bn2 = (const float*)d_in[7];
    const float* Wn3 = (const float*)d_in[8];
    const float* bn3 = (const float*)d_in[9];
    const float* We1 = (const float*)d_in[10];
    const float* be1 = (const float*)d_in[11];
    const float* We2 = (const float*)d_in[12];
    const float* be2 = (const float*)d_in[13];
    const float* We3 = (const float*)d_in[14];
    const float* be3 = (const float*)d_in[15];

    const int n_nodes = in_sizes[0] / DIM;
    const int n_edges = in_sizes[1] / DIM;
    const int G = out_size / (2 * DIM);

    cudaFuncSetAttribute(mlp_logits_kernel,
                         cudaFuncAttributeMaxDynamicSharedMemorySize, SMEM_BYTES);

    float* logits = nullptr;
    float* marr = nullptr;
    float* sarr = nullptr;
    cudaGetSymbolAddress((void**)&logits, g_logits);
    cudaGetSymbolAddress((void**)&marr, g_m);
    cudaGetSymbolAddress((void**)&sarr, g_s);

    float* logits_n = logits;
    float* logits_e = logits + n_nodes;
    float* m_n = marr;          float* s_n = sarr;
    float* m_e = marr + 2048;   float* s_e = sarr + 2048;

    int blocks_n = (n_nodes + TILE_ROWS - 1) / TILE_ROWS;
    int blocks_e = (n_edges + TILE_ROWS - 1) / TILE_ROWS;

    mlp_logits_kernel<<<blocks_n, THREADS, SMEM_BYTES>>>(
        emb_nodes, Wn1, bn1, Wn2, bn2, Wn3, bn3, logits_n, n_nodes);
    mlp_logits_kernel<<<blocks_e, THREADS, SMEM_BYTES>>>(
        emb_edges, We1, be1, We2, be2, We3, be3, logits_e, n_edges);

    seg_stats_kernel<<<G, 256>>>(logits_n, node_index, n_nodes, m_n, s_n);
    seg_stats_kernel<<<G, 256>>>(logits_e, edge_index, n_edges, m_e, s_e);

    float* out_n = (float*)d_out;
    float* out_e = (float*)d_out + (size_t)G * DIM;
    pool_kernel<<<G, 256>>>(emb_nodes, logits_n, node_index, m_n, s_n, out_n, n_nodes);
    pool_kernel<<<G, 256>>>(emb_edges, logits_e, edge_index, m_e, s_e, out_e, n_edges);
}

// round 8
// speedup vs baseline: 1.1136x; 1.1136x over previous
#include <cuda_runtime.h>
#include <cuda_fp16.h>
#include <mma.h>
#include <math.h>

using namespace nvcuda;

#define DIM 256
#define TILE_ROWS 128
#define THREADS 256
#define RPB 256   // rows per pool block

// smem layout for mlp kernel (bytes):
//  region0 : union( sXh half[128][264] , H1f float[128][132] ) = 67584
//  H1h     : half [128][136] = 34816   @ 67584
//  sb      : float[257] (b1[128],b2[64],W3[64],b3)  @ 102400 (pad 1040)
#define OFF_H1H 67584
#define OFF_B   102400
#define SMEM_BYTES (OFF_B + 1040)

// device scratch (no allocation allowed)
__device__ float g_logits[620000];
__device__ float g_m[4096];
__device__ float g_s[4096];
__device__ __half g_w1h[2][256 * 128];
__device__ __half g_w2h[2][128 * 64];

// ---------------- weight fp32 -> fp16 pre-convert ----------------
__global__ void convert_w_kernel(const float* __restrict__ W1,
                                 const float* __restrict__ W2,
                                 __half* __restrict__ o1, __half* __restrict__ o2)
{
    int i = blockIdx.x * 256 + threadIdx.x;
    if (i < 256 * 128) o1[i] = __float2half(W1[i]);
    if (i < 128 * 64)  o2[i] = __float2half(W2[i]);
}

// ---------------- MLP logits ----------------
__global__ void __launch_bounds__(THREADS, 2)
mlp_logits_kernel(const float* __restrict__ X,
                  const __half* __restrict__ W1h, const __half* __restrict__ W2h,
                  const float* __restrict__ b1, const float* __restrict__ b2,
                  const float* __restrict__ W3, const float* __restrict__ b3,
                  float* __restrict__ logits, int nrows)
{
    extern __shared__ char smem[];
    half*  sXh  = (half*)(smem);
    float* sH1f = (float*)(smem);
    float* sH2f = (float*)(smem);
    half*  sH1h = (half*)(smem + OFF_H1H);
    float* sb   = (float*)(smem + OFF_B);

    const int tid = threadIdx.x;
    const int w   = tid >> 5;
    const int rowBase = blockIdx.x * TILE_ROWS;

    if (tid < 128) sb[tid] = b1[tid];
    if (tid < 64) {
        sb[128 + tid] = b2[tid];
        sb[192 + tid] = W3[tid];
    }
    if (tid == 0) sb[256] = b3[0];

    // load X tile (fp32 -> fp16), vectorized, zero-pad tail rows
    {
        const float4* X4 = (const float4*)X;
#pragma unroll
        for (int k = 0; k < 32; k++) {
            int idx4 = tid + k * 256;          // over 128*64 float4s
            int r = idx4 >> 6, c4 = idx4 & 63;
            int gr = rowBase + r;
            float4 v = make_float4(0.f, 0.f, 0.f, 0.f);
            if (gr < nrows) v = X4[(size_t)gr * 64 + c4];
            half2 h0 = __floats2half2_rn(v.x, v.y);
            half2 h1 = __floats2half2_rn(v.z, v.w);
            uint2 pk;
            pk.x = *(unsigned int*)&h0;
            pk.y = *(unsigned int*)&h1;
            *(uint2*)(sXh + r * 264 + c4 * 4) = pk;
        }
    }
    __syncthreads();

    // ---- GEMM1: H1[128x128] = X[128x256] @ W1[256x128], B from global fp16 ----
    {
        wmma::fragment<wmma::accumulator, 16, 16, 16, float> acc[8];
#pragma unroll
        for (int n = 0; n < 8; n++) wmma::fill_fragment(acc[n], 0.0f);
#pragma unroll
        for (int kt = 0; kt < 16; kt++) {
            wmma::fragment<wmma::matrix_a, 16, 16, 16, half, wmma::row_major> a;
            wmma::load_matrix_sync(a, sXh + (w * 16) * 264 + kt * 16, 264);
#pragma unroll
            for (int n = 0; n < 8; n++) {
                wmma::fragment<wmma::matrix_b, 16, 16, 16, half, wmma::row_major> b;
                wmma::load_matrix_sync(b, W1h + (kt * 16) * 128 + n * 16, 128);
                wmma::mma_sync(acc[n], a, b, acc[n]);
            }
        }
        __syncthreads();  // all warps done reading sXh before overwriting region0
#pragma unroll
        for (int n = 0; n < 8; n++)
            wmma::store_matrix_sync(sH1f + (w * 16) * 132 + n * 16, acc[n], 132,
                                    wmma::mem_row_major);
    }
    __syncthreads();

    // bias + relu + convert to fp16
    for (int i = tid; i < 128 * 128; i += THREADS) {
        int r = i >> 7, c = i & 127;
        float v = sH1f[r * 132 + c] + sb[c];
        sH1h[r * 136 + c] = __float2half(fmaxf(v, 0.0f));
    }
    __syncthreads();

    // ---- GEMM2: H2[128x64] = H1[128x128] @ W2[128x64], B from global fp16 ----
    {
        wmma::fragment<wmma::accumulator, 16, 16, 16, float> acc2[4];
#pragma unroll
        for (int n = 0; n < 4; n++) wmma::fill_fragment(acc2[n], 0.0f);
#pragma unroll
        for (int kt = 0; kt < 8; kt++) {
            wmma::fragment<wmma::matrix_a, 16, 16, 16, half, wmma::row_major> a;
            wmma::load_matrix_sync(a, sH1h + (w * 16) * 136 + kt * 16, 136);
#pragma unroll
            for (int n = 0; n < 4; n++) {
                wmma::fragment<wmma::matrix_b, 16, 16, 16, half, wmma::row_major> b;
                wmma::load_matrix_sync(b, W2h + (kt * 16) * 64 + n * 16, 64);
                wmma::mma_sync(acc2[n], a, b, acc2[n]);
            }
        }
        // region0 holds stale H1f (fully consumed before last sync); each warp
        // stores only its own rows -> safe without extra sync
#pragma unroll
        for (int n = 0; n < 4; n++)
            wmma::store_matrix_sync(sH2f + (w * 16) * 68 + n * 16, acc2[n], 68,
                                    wmma::mem_row_major);
    }
    __syncthreads();

    // ---- layer 3: logit = b3 + sum_c relu(H2 + b2) * W3 ----
    if (tid < 128) {
        int r = tid;
        float acc = sb[256];
#pragma unroll
        for (int c = 0; c < 64; c++) {
            float v = fmaxf(sH2f[r * 68 + c] + sb[128 + c], 0.0f);
            acc = fmaf(v, sb[192 + c], acc);
        }
        int gr = rowBase + r;
        if (gr < nrows) logits[gr] = acc;
    }
}

// ---------------- segment stats (max, sum-exp) ----------------
__device__ __forceinline__ int lower_bound_idx(const int* __restrict__ index,
                                               int n, int target)
{
    int lo = 0, hi = n;
    while (lo < hi) {
        int mid = (lo + hi) >> 1;
        if (index[mid] < target) lo = mid + 1; else hi = mid;
    }
    return lo;
}

__global__ void __launch_bounds__(256)
seg_stats_kernel(const float* __restrict__ logits, const int* __restrict__ index,
                 int n, float* __restrict__ m_out, float* __restrict__ s_out)
{
    __shared__ int sse[2];
    __shared__ float red[8];
    int g = blockIdx.x;
    if (threadIdx.x < 2) sse[threadIdx.x] = lower_bound_idx(index, n, g + (int)threadIdx.x);
    __syncthreads();
    int start = sse[0], end = sse[1];
    int tid = threadIdx.x, lane = tid & 31, warp = tid >> 5;

    float m = -INFINITY;
    for (int i = start + tid; i < end; i += 256) m = fmaxf(m, logits[i]);
#pragma unroll
    for (int off = 16; off; off >>= 1) m = fmaxf(m, __shfl_xor_sync(0xffffffffu, m, off));
    if (lane == 0) red[warp] = m;
    __syncthreads();
    if (tid == 0) {
        float mm = red[0];
#pragma unroll
        for (int i = 1; i < 8; i++) mm = fmaxf(mm, red[i]);
        red[0] = mm;
    }
    __syncthreads();
    m = red[0];
    __syncthreads();

    float s = 0.0f;
    for (int i = start + tid; i < end; i += 256) s += __expf(logits[i] - m);
#pragma unroll
    for (int off = 16; off; off >>= 1) s += __shfl_xor_sync(0xffffffffu, s, off);
    if (lane == 0) red[warp] = s;
    __syncthreads();
    if (tid == 0) {
        float ss = 0.0f;
#pragma unroll
        for (int i = 0; i < 8; i++) ss += red[i];
        m_out[g] = (end > start) ? m : 0.0f;
        s_out[g] = (end > start) ? ss : 1.0f;
    }
}

// ---------------- logits -> softmax weights (in-place) ----------------
__global__ void __launch_bounds__(256)
apply_w_kernel(float* __restrict__ logits, const int* __restrict__ index,
               const float* __restrict__ m_arr, const float* __restrict__ s_arr,
               int n)
{
    int i = blockIdx.x * 256 + threadIdx.x;
    if (i < n) {
        int g = index[i];
        logits[i] = __fdividef(__expf(logits[i] - m_arr[g]), s_arr[g]);
    }
}

// ---------------- row-tiled weighted segment sum ----------------
__global__ void __launch_bounds__(256)
pool_kernel(const float* __restrict__ X, const float* __restrict__ wrow,
            const int* __restrict__ index, float* __restrict__ out, int n)
{
    __shared__ float sw[RPB];
    __shared__ int sstart[2052];   // run starts (local), worst case many empty graphs
    const int base = blockIdx.x * RPB;
    const int cnt = min(RPB, n - base);
    const int tid = threadIdx.x;

    for (int i = tid; i < cnt; i += 256) sw[i] = wrow[base + i];

    const int g0 = index[base];
    const int g1 = index[base + cnt - 1];
    const int nruns = g1 - g0 + 1;

    for (int t = tid; t < nruns; t += 256) {
        int gs = lower_bound_idx(index, n, g0 + t) - base;
        sstart[t] = max(gs, 0);
    }
    if (tid == 0) sstart[nruns] = cnt;
    __syncthreads();

    const int d = tid;
    for (int run = 0; run < nruns; run++) {
        int rs = sstart[run], re = sstart[run + 1];
        if (rs >= re) continue;
        float a0 = 0.f, a1 = 0.f, a2 = 0.f, a3 = 0.f;
        int i = rs;
        for (; i + 3 < re; i += 4) {
            a0 = fmaf(sw[i + 0], X[(size_t)(base + i + 0) * DIM + d], a0);
            a1 = fmaf(sw[i + 1], X[(size_t)(base + i + 1) * DIM + d], a1);
            a2 = fmaf(sw[i + 2], X[(size_t)(base + i + 2) * DIM + d], a2);
            a3 = fmaf(sw[i + 3], X[(size_t)(base + i + 3) * DIM + d], a3);
        }
        for (; i < re; i++)
            a0 = fmaf(sw[i], X[(size_t)(base + i) * DIM + d], a0);
        float acc = (a0 + a1) + (a2 + a3);
        atomicAdd(&out[(size_t)(g0 + run) * DIM + d], acc);
    }
}

extern "C" void kernel_launch(void* const* d_in, const int* in_sizes, int n_in,
                              void* d_out, int out_size)
{
    const float* emb_nodes  = (const float*)d_in[0];
    const float* emb_edges  = (const float*)d_in[1];
    const int*   node_index = (const int*)d_in[2];
    const int*   edge_index = (const int*)d_in[3];
    const float* Wn1 = (const float*)d_in[4];
    const float* bn1 = (const float*)d_in[5];
    const float* Wn2 = (const float*)d_in[6];
    const float* bn2 = (const float*)d_in[7];
    const float* Wn3 = (const float*)d_in[8];
    const float* bn3 = (const float*)d_in[9];
    const float* We1 = (const float*)d_in[10];
    const float* be1 = (const float*)d_in[11];
    const float* We2 = (const float*)d_in[12];
    const float* be2 = (const float*)d_in[13];
    const float* We3 = (const float*)d_in[14];
    const float* be3 = (const float*)d_in[15];

    const int n_nodes = in_sizes[0] / DIM;
    const int n_edges = in_sizes[1] / DIM;
    const int G = out_size / (2 * DIM);

    cudaFuncSetAttribute(mlp_logits_kernel,
                         cudaFuncAttributeMaxDynamicSharedMemorySize, SMEM_BYTES);

    float* logits = nullptr;  float* marr = nullptr;  float* sarr = nullptr;
    __half* w1h = nullptr;    __half* w2h = nullptr;
    cudaGetSymbolAddress((void**)&logits, g_logits);
    cudaGetSymbolAddress((void**)&marr, g_m);
    cudaGetSymbolAddress((void**)&sarr, g_s);
    cudaGetSymbolAddress((void**)&w1h, g_w1h);
    cudaGetSymbolAddress((void**)&w2h, g_w2h);

    __half* w1h_n = w1h;               __half* w2h_n = w2h;
    __half* w1h_e = w1h + 256 * 128;   __half* w2h_e = w2h + 128 * 64;

    float* logits_n = logits;
    float* logits_e = logits + n_nodes;
    float* m_n = marr;          float* s_n = sarr;
    float* m_e = marr + 2048;   float* s_e = sarr + 2048;

    float* out_n = (float*)d_out;
    float* out_e = (float*)d_out + (size_t)G * DIM;

    // zero output (atomic accumulation target)
    cudaMemsetAsync(d_out, 0, (size_t)out_size * sizeof(float));

    // weight pre-convert (fp32 -> fp16 global)
    convert_w_kernel<<<128, 256>>>(Wn1, Wn2, w1h_n, w2h_n);
    convert_w_kernel<<<128, 256>>>(We1, We2, w1h_e, w2h_e);

    int blocks_n = (n_nodes + TILE_ROWS - 1) / TILE_ROWS;
    int blocks_e = (n_edges + TILE_ROWS - 1) / TILE_ROWS;

    mlp_logits_kernel<<<blocks_n, THREADS, SMEM_BYTES>>>(
        emb_nodes, w1h_n, w2h_n, bn1, bn2, Wn3, bn3, logits_n, n_nodes);
    mlp_logits_kernel<<<blocks_e, THREADS, SMEM_BYTES>>>(
        emb_edges, w1h_e, w2h_e, be1, be2, We3, be3, logits_e, n_edges);

    seg_stats_kernel<<<G, 256>>>(logits_n, node_index, n_nodes, m_n, s_n);
    seg_stats_kernel<<<G, 256>>>(logits_e, edge_index, n_edges, m_e, s_e);

    apply_w_kernel<<<(n_nodes + 255) / 256, 256>>>(logits_n, node_index, m_n, s_n, n_nodes);
    apply_w_kernel<<<(n_edges + 255) / 256, 256>>>(logits_e, edge_index, m_e, s_e, n_edges);

    pool_kernel<<<(n_nodes + RPB - 1) / RPB, 256>>>(emb_nodes, logits_n, node_index, out_n, n_nodes);
    pool_kernel<<<(n_edges + RPB - 1) / RPB, 256>>>(emb_edges, logits_e, edge_index, out_e, n_edges);
}

// round 11
// speedup vs baseline: 2.5658x; 2.3041x over previous
#include <cuda_runtime.h>
#include <cuda_fp16.h>
#include <mma.h>
#include <math.h>

using namespace nvcuda;

#define DIM 256
#define TILE_ROWS 128
#define THREADS 256
#define RPB 256   // rows per pool block

// smem layout (bytes):
//  sW1h : half [256][136] = 69632            @ 0
//  sW2h : half [128][72]  = 18432            @ 69632
//  region C (union):                          @ 88064
//     sXh  : half  [128][264] = 67584
//     sH1f : float [128][132] = 67584
//     sH2f : float [128][68]  = 34816
//  sH1h : half [128][136] = 34816            @ 155648
//  sb   : float[257]                          @ 190464 (pad 1040)
#define OFF_W1  0
#define OFF_W2  69632
#define OFF_C   88064
#define OFF_H1H 155648
#define OFF_B   190464
#define SMEM_BYTES (OFF_B + 1040)

// device scratch (no allocation allowed)
__device__ float g_logits[620000];
__device__ float g_m[4096];
__device__ float g_s[4096];
__device__ __half g_w1h[2][256 * 128];
__device__ __half g_w2h[2][128 * 64];

// ---------------- weight fp32 -> fp16 pre-convert (once) ----------------
__global__ void convert_w_kernel(const float* __restrict__ W1,
                                 const float* __restrict__ W2,
                                 __half* __restrict__ o1, __half* __restrict__ o2)
{
    int i = blockIdx.x * 256 + threadIdx.x;
    if (i < 256 * 128) o1[i] = __float2half(W1[i]);
    if (i < 128 * 64)  o2[i] = __float2half(W2[i]);
}

// ---------------- MLP logits ----------------
__global__ void __launch_bounds__(THREADS)
mlp_logits_kernel(const float* __restrict__ X,
                  const __half* __restrict__ W1h, const __half* __restrict__ W2h,
                  const float* __restrict__ b1, const float* __restrict__ b2,
                  const float* __restrict__ W3, const float* __restrict__ b3,
                  float* __restrict__ logits, int nrows)
{
    extern __shared__ char smem[];
    half*  sW1h = (half*)(smem + OFF_W1);
    half*  sW2h = (half*)(smem + OFF_W2);
    half*  sXh  = (half*)(smem + OFF_C);
    float* sH1f = (float*)(smem + OFF_C);
    float* sH2f = (float*)(smem + OFF_C);
    half*  sH1h = (half*)(smem + OFF_H1H);
    float* sb   = (float*)(smem + OFF_B);

    const int tid = threadIdx.x;
    const int w   = tid >> 5;
    const int rowBase = blockIdx.x * TILE_ROWS;

    // ---- stage weights: vectorized uint4 copy of pre-converted fp16 ----
    {
        const uint4* W1v = (const uint4*)W1h;   // 4096 uint4 (8 halfs each)
#pragma unroll
        for (int k = 0; k < 16; k++) {
            int idx8 = tid + k * 256;
            int r = idx8 >> 4, c8 = idx8 & 15;   // 128 cols / 8 = 16 chunks
            *(uint4*)(sW1h + r * 136 + c8 * 8) = W1v[idx8];
        }
        const uint4* W2v = (const uint4*)W2h;   // 1024 uint4
#pragma unroll
        for (int k = 0; k < 4; k++) {
            int idx8 = tid + k * 256;
            int r = idx8 >> 3, c8 = idx8 & 7;    // 64 cols / 8 = 8 chunks
            *(uint4*)(sW2h + r * 72 + c8 * 8) = W2v[idx8];
        }
    }
    if (tid < 128) sb[tid] = b1[tid];
    if (tid < 64) {
        sb[128 + tid] = b2[tid];
        sb[192 + tid] = W3[tid];
    }
    if (tid == 0) sb[256] = b3[0];

    // ---- load X tile (fp32 -> fp16), vectorized, zero-pad tail rows ----
    {
        const float4* X4 = (const float4*)X;
#pragma unroll
        for (int k = 0; k < 32; k++) {
            int idx4 = tid + k * 256;            // over 128*64 float4s
            int r = idx4 >> 6, c4 = idx4 & 63;
            int gr = rowBase + r;
            float4 v = make_float4(0.f, 0.f, 0.f, 0.f);
            if (gr < nrows) v = X4[(size_t)gr * 64 + c4];
            half2 h0 = __floats2half2_rn(v.x, v.y);
            half2 h1 = __floats2half2_rn(v.z, v.w);
            uint2 pk;
            pk.x = *(unsigned int*)&h0;
            pk.y = *(unsigned int*)&h1;
            *(uint2*)(sXh + r * 264 + c4 * 4) = pk;
        }
    }
    __syncthreads();

    // ---- GEMM1: H1[128x128] = X[128x256] @ W1[256x128] ----
    // warp tiling: 4 M-groups x 2 N-groups; each warp computes 32 rows x 64 cols
    {
        const int mBase = (w >> 1) * 32;        // 0,32,64,96
        const int nBase = (w & 1) * 64;         // 0,64
        wmma::fragment<wmma::accumulator, 16, 16, 16, float> acc[2][4];
#pragma unroll
        for (int m = 0; m < 2; m++)
#pragma unroll
            for (int n = 0; n < 4; n++) wmma::fill_fragment(acc[m][n], 0.0f);
#pragma unroll
        for (int kt = 0; kt < 16; kt++) {
            wmma::fragment<wmma::matrix_a, 16, 16, 16, half, wmma::row_major> a[2];
#pragma unroll
            for (int m = 0; m < 2; m++)
                wmma::load_matrix_sync(a[m], sXh + (mBase + m * 16) * 264 + kt * 16, 264);
#pragma unroll
            for (int n = 0; n < 4; n++) {
                wmma::fragment<wmma::matrix_b, 16, 16, 16, half, wmma::row_major> b;
                wmma::load_matrix_sync(b, sW1h + (kt * 16) * 136 + nBase + n * 16, 136);
#pragma unroll
                for (int m = 0; m < 2; m++)
                    wmma::mma_sync(acc[m][n], a[m], b, acc[m][n]);
            }
        }
        __syncthreads();  // all warps done reading sXh before overwriting region C
#pragma unroll
        for (int m = 0; m < 2; m++)
#pragma unroll
            for (int n = 0; n < 4; n++)
                wmma::store_matrix_sync(sH1f + (mBase + m * 16) * 132 + nBase + n * 16,
                                        acc[m][n], 132, wmma::mem_row_major);
    }
    __syncthreads();

    // ---- bias + relu + convert to fp16 (vectorized: float2 -> half2) ----
    for (int i = tid; i < 128 * 64; i += THREADS) {
        int r = i >> 6, c2 = i & 63;
        float2 v = *(const float2*)(sH1f + r * 132 + c2 * 2);
        float b0 = sb[c2 * 2], b1v = sb[c2 * 2 + 1];
        half2 h = __floats2half2_rn(fmaxf(v.x + b0, 0.0f), fmaxf(v.y + b1v, 0.0f));
        *(half2*)(sH1h + r * 136 + c2 * 2) = h;
    }
    __syncthreads();

    // ---- GEMM2: H2[128x64] = H1[128x128] @ W2[128x64] ----
    {
        wmma::fragment<wmma::accumulator, 16, 16, 16, float> acc2[4];
#pragma unroll
        for (int n = 0; n < 4; n++) wmma::fill_fragment(acc2[n], 0.0f);
#pragma unroll
        for (int kt = 0; kt < 8; kt++) {
            wmma::fragment<wmma::matrix_a, 16, 16, 16, half, wmma::row_major> a;
            wmma::load_matrix_sync(a, sH1h + (w * 16) * 136 + kt * 16, 136);
#pragma unroll
            for (int n = 0; n < 4; n++) {
                wmma::fragment<wmma::matrix_b, 16, 16, 16, half, wmma::row_major> b;
                wmma::load_matrix_sync(b, sW2h + (kt * 16) * 72 + n * 16, 72);
                wmma::mma_sync(acc2[n], a, b, acc2[n]);
            }
        }
        // region C holds stale H1f (fully consumed before last sync); safe to store
#pragma unroll
        for (int n = 0; n < 4; n++)
            wmma::store_matrix_sync(sH2f + (w * 16) * 68 + n * 16, acc2[n], 68,
                                    wmma::mem_row_major);
    }
    __syncthreads();

    // ---- layer 3: logit = b3 + sum_c relu(H2 + b2) * W3 ----
    if (tid < 128) {
        int r = tid;
        float acc = sb[256];
#pragma unroll
        for (int c = 0; c < 64; c++) {
            float v = fmaxf(sH2f[r * 68 + c] + sb[128 + c], 0.0f);
            acc = fmaf(v, sb[192 + c], acc);
        }
        int gr = rowBase + r;
        if (gr < nrows) logits[gr] = acc;
    }
}

// ---------------- segment stats (max, sum-exp) ----------------
__device__ __forceinline__ int lower_bound_idx(const int* __restrict__ index,
                                               int n, int target)
{
    int lo = 0, hi = n;
    while (lo < hi) {
        int mid = (lo + hi) >> 1;
        if (index[mid] < target) lo = mid + 1; else hi = mid;
    }
    return lo;
}

__global__ void __launch_bounds__(256)
seg_stats_kernel(const float* __restrict__ logits, const int* __restrict__ index,
                 int n, float* __restrict__ m_out, float* __restrict__ s_out)
{
    __shared__ int sse[2];
    __shared__ float red[8];
    int g = blockIdx.x;
    if (threadIdx.x < 2) sse[threadIdx.x] = lower_bound_idx(index, n, g + (int)threadIdx.x);
    __syncthreads();
    int start = sse[0], end = sse[1];
    int tid = threadIdx.x, lane = tid & 31, warp = tid >> 5;

    float m = -INFINITY;
    for (int i = start + tid; i < end; i += 256) m = fmaxf(m, logits[i]);
#pragma unroll
    for (int off = 16; off; off >>= 1) m = fmaxf(m, __shfl_xor_sync(0xffffffffu, m, off));
    if (lane == 0) red[warp] = m;
    __syncthreads();
    if (tid == 0) {
        float mm = red[0];
#pragma unroll
        for (int i = 1; i < 8; i++) mm = fmaxf(mm, red[i]);
        red[0] = mm;
    }
    __syncthreads();
    m = red[0];
    __syncthreads();

    float s = 0.0f;
    for (int i = start + tid; i < end; i += 256) s += __expf(logits[i] - m);
#pragma unroll
    for (int off = 16; off; off >>= 1) s += __shfl_xor_sync(0xffffffffu, s, off);
    if (lane == 0) red[warp] = s;
    __syncthreads();
    if (tid == 0) {
        float ss = 0.0f;
#pragma unroll
        for (int i = 0; i < 8; i++) ss += red[i];
        m_out[g] = (end > start) ? m : 0.0f;
        s_out[g] = (end > start) ? ss : 1.0f;
    }
}

// ---------------- logits -> softmax weights (in-place) ----------------
__global__ void __launch_bounds__(256)
apply_w_kernel(float* __restrict__ logits, const int* __restrict__ index,
               const float* __restrict__ m_arr, const float* __restrict__ s_arr,
               int n)
{
    int i = blockIdx.x * 256 + threadIdx.x;
    if (i < n) {
        int g = index[i];
        logits[i] = __fdividef(__expf(logits[i] - m_arr[g]), s_arr[g]);
    }
}

// ---------------- row-tiled weighted segment sum ----------------
__global__ void __launch_bounds__(256)
pool_kernel(const float* __restrict__ X, const float* __restrict__ wrow,
            const int* __restrict__ index, float* __restrict__ out, int n)
{
    __shared__ float sw[RPB];
    __shared__ int sstart[2052];
    const int base = blockIdx.x * RPB;
    const int cnt = min(RPB, n - base);
    const int tid = threadIdx.x;

    for (int i = tid; i < cnt; i += 256) sw[i] = wrow[base + i];

    const int g0 = index[base];
    const int g1 = index[base + cnt - 1];
    const int nruns = g1 - g0 + 1;

    for (int t = tid; t < nruns; t += 256) {
        int gs = lower_bound_idx(index, n, g0 + t) - base;
        sstart[t] = max(gs, 0);
    }
    if (tid == 0) sstart[nruns] = cnt;
    __syncthreads();

    const int d = tid;
    for (int run = 0; run < nruns; run++) {
        int rs = sstart[run], re = sstart[run + 1];
        if (rs >= re) continue;
        float a0 = 0.f, a1 = 0.f, a2 = 0.f, a3 = 0.f;
        int i = rs;
        for (; i + 3 < re; i += 4) {
            a0 = fmaf(sw[i + 0], X[(size_t)(base + i + 0) * DIM + d], a0);
            a1 = fmaf(sw[i + 1], X[(size_t)(base + i + 1) * DIM + d], a1);
            a2 = fmaf(sw[i + 2], X[(size_t)(base + i + 2) * DIM + d], a2);
            a3 = fmaf(sw[i + 3], X[(size_t)(base + i + 3) * DIM + d], a3);
        }
        for (; i < re; i++)
            a0 = fmaf(sw[i], X[(size_t)(base + i) * DIM + d], a0);
        float acc = (a0 + a1) + (a2 + a3);
        atomicAdd(&out[(size_t)(g0 + run) * DIM + d], acc);
    }
}

extern "C" void kernel_launch(void* const* d_in, const int* in_sizes, int n_in,
                              void* d_out, int out_size)
{
    const float* emb_nodes  = (const float*)d_in[0];
    const float* emb_edges  = (const float*)d_in[1];
    const int*   node_index = (const int*)d_in[2];
    const int*   edge_index = (const int*)d_in[3];
    const float* Wn1 = (const float*)d_in[4];
    const float* bn1 = (const float*)d_in[5];
    const float* Wn2 = (const float*)d_in[6];
    const float* bn2 = (const float*)d_in[7];
    const float* Wn3 = (const float*)d_in[8];
    const float* bn3 = (const float*)d_in[9];
    const float* We1 = (const float*)d_in[10];
    const float* be1 = (const float*)d_in[11];
    const float* We2 = (const float*)d_in[12];
    const float* be2 = (const float*)d_in[13];
    const float* We3 = (const float*)d_in[14];
    const float* be3 = (const float*)d_in[15];

    const int n_nodes = in_sizes[0] / DIM;
    const int n_edges = in_sizes[1] / DIM;
    const int G = out_size / (2 * DIM);

    cudaFuncSetAttribute(mlp_logits_kernel,
                         cudaFuncAttributeMaxDynamicSharedMemorySize, SMEM_BYTES);

    float* logits = nullptr;  float* marr = nullptr;  float* sarr = nullptr;
    __half* w1h = nullptr;    __half* w2h = nullptr;
    cudaGetSymbolAddress((void**)&logits, g_logits);
    cudaGetSymbolAddress((void**)&marr, g_m);
    cudaGetSymbolAddress((void**)&sarr, g_s);
    cudaGetSymbolAddress((void**)&w1h, g_w1h);
    cudaGetSymbolAddress((void**)&w2h, g_w2h);

    __half* w1h_n = w1h;               __half* w2h_n = w2h;
    __half* w1h_e = w1h + 256 * 128;   __half* w2h_e = w2h + 128 * 64;

    float* logits_n = logits;
    float* logits_e = logits + n_nodes;
    float* m_n = marr;          float* s_n = sarr;
    float* m_e = marr + 2048;   float* s_e = sarr + 2048;

    float* out_n = (float*)d_out;
    float* out_e = (float*)d_out + (size_t)G * DIM;

    cudaMemsetAsync(d_out, 0, (size_t)out_size * sizeof(float));

    convert_w_kernel<<<128, 256>>>(Wn1, Wn2, w1h_n, w2h_n);
    convert_w_kernel<<<128, 256>>>(We1, We2, w1h_e, w2h_e);

    int blocks_n = (n_nodes + TILE_ROWS - 1) / TILE_ROWS;
    int blocks_e = (n_edges + TILE_ROWS - 1) / TILE_ROWS;

    mlp_logits_kernel<<<blocks_n, THREADS, SMEM_BYTES>>>(
        emb_nodes, w1h_n, w2h_n, bn1, bn2, Wn3, bn3, logits_n, n_nodes);
    mlp_logits_kernel<<<blocks_e, THREADS, SMEM_BYTES>>>(
        emb_edges, w1h_e, w2h_e, be1, be2, We3, be3, logits_e, n_edges);

    seg_stats_kernel<<<G, 256>>>(logits_n, node_index, n_nodes, m_n, s_n);
    seg_stats_kernel<<<G, 256>>>(logits_e, edge_index, n_edges, m_e, s_e);

    apply_w_kernel<<<(n_nodes + 255) / 256, 256>>>(logits_n, node_index, m_n, s_n, n_nodes);
    apply_w_kernel<<<(n_edges + 255) / 256, 256>>>(logits_e, edge_index, m_e, s_e, n_edges);

    pool_kernel<<<(n_nodes + RPB - 1) / RPB, 256>>>(emb_nodes, logits_n, node_index, out_n, n_nodes);
    pool_kernel<<<(n_edges + RPB - 1) / RPB, 256>>>(emb_edges, logits_e, edge_index, out_e, n_edges);
}